// round 16
// baseline (speedup 1.0000x reference)
#include <cuda_runtime.h>
#include <math.h>

#define NEGV (-1e30f)
#define LN2F 0.6931471805599453f

// scratch (no cudaMalloc allowed)
__device__ float g_alpha[64 * 520];
__device__ float g_beta[64 * 520];
__device__ float g_loss[4096];
__device__ unsigned g_done[4096];   // 2 incs per b per launch, wraps 0->1->0
__device__ unsigned g_ctr;          // B incs per launch, wraps to 0

__device__ __forceinline__ float ex2(float x) {
    float r; asm("ex2.approx.f32 %0, %1;" : "=f"(r) : "f"(x)); return r;
}
__device__ __forceinline__ float lg2(float x) {
    float r; asm("lg2.approx.f32 %0, %1;" : "=f"(r) : "f"(x)); return r;
}
__device__ __forceinline__ int imin(int a, int b) { return a < b ? a : b; }
__device__ __forceinline__ int imax(int a, int b) { return a > b ? a : b; }

// ---------------------------------------------------------------------------
// Fused kernel (blockDim = 256):
//   blocks [0, B)        : CTC forward half  (t = 0 .. tm)      [log2 domain]
//   blocks [B, 2B)       : CTC backward half (t = il-1 .. tm)   [log2 domain]
//   blocks [2B, grid)    : log + transpose  out[t,b,c] = log(p[b,t,c])
// Probability streams are double-buffered in registers (A/B, 8 steps each);
// refills are batched between phases so the step body has NO global loads.
// Second finisher of each (fwd, bwd) pair combines: loss = -lse_s(alpha+beta).
// ---------------------------------------------------------------------------
__global__ void __launch_bounds__(256)
ctc_fused_kernel(const float* __restrict__ p,      // [B,T,C]
                 const int* __restrict__ labels,   // [B,L]
                 const int* __restrict__ in_len,   // [B]
                 const int* __restrict__ lab_len,  // [B]
                 float* __restrict__ out,          // [T,B,C] (+ loss at end)
                 int T, int B, int C, int L,
                 long long loss_idx) {
    const int bx = blockIdx.x;
    if (bx >= 2 * B) {
        // ---------------- log + transpose (float4) --------------------------
        const int c4w = C >> 2;
        const long long total4 = (long long)T * B * c4w;
        const float4* __restrict__ p4 = (const float4*)p;
        float4* __restrict__ o4 = (float4*)out;
        const long long stride = (long long)(gridDim.x - 2 * B) * blockDim.x;
        for (long long v = (long long)(bx - 2 * B) * blockDim.x + threadIdx.x;
             v < total4; v += stride) {
            int c4 = (int)(v % c4w);
            long long rr = v / c4w;          // rr = t*B + b
            int b = (int)(rr % B);
            long long t = rr / B;
            float4 x = p4[((long long)b * T + t) * c4w + c4];
            float4 y;
            y.x = __logf(x.x); y.y = __logf(x.y);
            y.z = __logf(x.z); y.w = __logf(x.w);
            o4[v] = y;
        }
        return;
    }

    __shared__ float bnd[2][8];
    __shared__ float red[8];
    __shared__ unsigned sflag;

    const bool isFwd = (bx < B);
    const int b    = isFwd ? bx : bx - B;
    const int tid  = threadIdx.x;
    const int w    = tid >> 5;
    const int lane = tid & 31;
    const int last = blockDim.x - 1;

    int il = in_len[b];  il = il < 1 ? 1 : (il > T ? T : il);
    int ll = lab_len[b]; ll = ll < 1 ? 1 : (ll > L ? L : ll);
    const int tm = (il - 1) >> 1;            // meeting time

    const float* __restrict__ pbase = p + (long long)b * T * C;   // blank col 0

    if (isFwd) {
        // ===== forward: thread owns alpha(2tid)=ae, alpha(2tid+1)=ao ========
        // dep: left neighbor's old ao (state 2tid-1); last thread owns 512.
        const int   lab = labels[b * L + tid];
        const float ks  = ((tid > 0) && (lab != labels[b * L + tid - 1])) ? 1.0f : 0.0f;
        const float* __restrict__ plabp = pbase + lab;

        float ae, ao, a5 = NEGV;
        {
            float pb0 = __ldg(pbase);
            float pl0 = __ldg(plabp);
            ae = (tid == 0) ? lg2(pb0) : NEGV;
            ao = (tid == 0) ? lg2(pl0) : NEGV;
            if (lane == 31) bnd[1][w] = ao;     // parity for t=1
        }

        // prob buffers: A holds steps tb..tb+7, B holds tb+8..tb+15
        float pbA[8], plA[8], pbB[8], plB[8];
        #pragma unroll
        for (int j = 0; j < 8; ++j) {
            int t1 = imin(1 + j, il - 1);
            int t2 = imin(9 + j, il - 1);
            pbA[j] = __ldg(pbase + (long long)t1 * C);
            plA[j] = __ldg(plabp + (long long)t1 * C);
            pbB[j] = __ldg(pbase + (long long)t2 * C);
            plB[j] = __ldg(plabp + (long long)t2 * C);
        }
        __syncthreads();

        #define FSTEP(T_, PB_, PL_)                                          \
        {                                                                     \
            const int t_ = (T_);                                              \
            float pb = (PB_), pl = (PL_);                                     \
            float a_ol = __shfl_up_sync(0xffffffffu, ao, 1);                  \
            if (lane == 0) a_ol = (w > 0) ? bnd[t_ & 1][w - 1] : NEGV;        \
            float m  = fmaxf(fmaxf(ae, ao), a_ol);                            \
            float xe = ex2(ae - m);                                           \
            float xo = ex2(ao - m);                                           \
            float xL = ex2(a_ol - m);                                         \
            float ve = m + lg2((xe + xL) * pb);                               \
            float vo = m + lg2((xo + xe + ks * xL) * pl);                     \
            if (tid == last) {                                                \
                float m5 = fmaxf(a5, ao);                                     \
                a5 = fmaxf(m5 + lg2((ex2(a5 - m5) + ex2(ao - m5)) * pb), NEGV); \
            }                                                                 \
            ae = fmaxf(ve, NEGV);                                             \
            ao = fmaxf(vo, NEGV);                                             \
            if (lane == 31) bnd[(t_ + 1) & 1][w] = ao;                        \
            __syncthreads();                                                  \
        }

        const int tend = tm + 1;                  // loop t = 1 .. tm
        for (int tb = 1; tb < tend; tb += 16) {
            // phase A: steps tb .. tb+7
            #pragma unroll
            for (int j = 0; j < 8; ++j) {
                int t = tb + j;
                if (t >= tend) break;             // uniform across block
                FSTEP(t, pbA[j], plA[j]);
            }
            // refill A <- steps tb+16 .. tb+23 (used next iteration phase A)
            if (tb + 16 < tend) {
                #pragma unroll
                for (int j = 0; j < 8; ++j) {
                    int tt = imin(tb + 16 + j, il - 1);
                    pbA[j] = __ldg(pbase + (long long)tt * C);
                    plA[j] = __ldg(plabp + (long long)tt * C);
                }
            }
            // phase B: steps tb+8 .. tb+15
            #pragma unroll
            for (int j = 0; j < 8; ++j) {
                int t = tb + 8 + j;
                if (t >= tend) break;             // uniform across block
                FSTEP(t, pbB[j], plB[j]);
            }
            // refill B <- steps tb+24 .. tb+31 (used next iteration phase B)
            if (tb + 24 < tend) {
                #pragma unroll
                for (int j = 0; j < 8; ++j) {
                    int tt = imin(tb + 24 + j, il - 1);
                    pbB[j] = __ldg(pbase + (long long)tt * C);
                    plB[j] = __ldg(plabp + (long long)tt * C);
                }
            }
        }
        #undef FSTEP

        float* ga = g_alpha + b * 520;
        ga[2 * tid]     = ae;
        ga[2 * tid + 1] = ao;
        if (tid == last) ga[512] = a5;
    } else {
        // ===== backward: thread owns beta(2tid+1)=bo, beta(2tid+2)=be =======
        // dep: right neighbor's old bo (state 2tid+3); thread 0 owns beta(0).
        const int   lab0 = labels[b * L + tid];
        const int   labN = (tid < last) ? labels[b * L + tid + 1] : lab0;
        const float ksN  = ((tid < last) && (labN != lab0)) ? 1.0f : 0.0f;
        const float* __restrict__ pl0p = pbase + lab0;
        const float* __restrict__ plNp = pbase + labN;

        float bo = (tid == ll - 1) ? 0.0f : NEGV;   // state 2tid+1
        float be = (tid == ll - 1) ? 0.0f : NEGV;   // state 2tid+2
        float b0 = NEGV;                             // state 0 (thread 0)
        if (lane == 0 && w > 0) bnd[0][w] = bo;      // consumed at k=0 by w-1

        const int nsteps = il - 1 - tm;           // k = 0 .. nsteps-1
        // prob buffers: slot j of A holds time il-1-(kb+j); B is kb+8..kb+15
        float qbA[8], q0A[8], qNA[8], qbB[8], q0B[8], qNB[8];
        #pragma unroll
        for (int j = 0; j < 8; ++j) {
            int t1 = imax(il - 1 - j, 0);
            int t2 = imax(il - 9 - j, 0);
            qbA[j] = __ldg(pbase + (long long)t1 * C);
            q0A[j] = __ldg(pl0p  + (long long)t1 * C);
            qNA[j] = __ldg(plNp  + (long long)t1 * C);
            qbB[j] = __ldg(pbase + (long long)t2 * C);
            q0B[j] = __ldg(pl0p  + (long long)t2 * C);
            qNB[j] = __ldg(plNp  + (long long)t2 * C);
        }
        __syncthreads();

        #define BSTEP(K_, QB_, Q0_, QN_)                                     \
        {                                                                     \
            const int k_ = (K_);                                              \
            float qb = (QB_), q0 = (Q0_), qN = (QN_);                         \
            float boN = __shfl_down_sync(0xffffffffu, bo, 1);                 \
            if (lane == 31) boN = (w < 7) ? bnd[k_ & 1][w + 1] : NEGV;        \
            float m  = fmaxf(fmaxf(bo, be), boN);                             \
            float xo = ex2(bo - m);                                           \
            float xe = ex2(be - m);                                           \
            float xN = ex2(boN - m);                                          \
            float t1 = xe * qb;                                               \
            float t2 = xN * qN;                                               \
            float nbo = m + lg2(xo * q0 + t1 + ksN * t2);                     \
            float nbe = m + lg2(t1 + t2);                                     \
            if (tid == 0) {                                                   \
                float mb = fmaxf(b0, bo);                                     \
                b0 = fmaxf(mb + lg2(ex2(b0 - mb) * qb + ex2(bo - mb) * q0), NEGV); \
            }                                                                 \
            bo = fmaxf(nbo, NEGV);                                            \
            be = fmaxf(nbe, NEGV);                                            \
            if (lane == 0 && w > 0) bnd[(k_ + 1) & 1][w] = bo;                \
            __syncthreads();                                                  \
        }

        for (int kb = 0; kb < nsteps; kb += 16) {
            // phase A: k = kb .. kb+7
            #pragma unroll
            for (int j = 0; j < 8; ++j) {
                int k = kb + j;
                if (k >= nsteps) break;           // uniform across block
                BSTEP(k, qbA[j], q0A[j], qNA[j]);
            }
            // refill A <- k = kb+16 .. kb+23
            if (kb + 16 < nsteps) {
                #pragma unroll
                for (int j = 0; j < 8; ++j) {
                    int tq = imax(il - 1 - (kb + 16 + j), 0);
                    qbA[j] = __ldg(pbase + (long long)tq * C);
                    q0A[j] = __ldg(pl0p  + (long long)tq * C);
                    qNA[j] = __ldg(plNp  + (long long)tq * C);
                }
            }
            // phase B: k = kb+8 .. kb+15
            #pragma unroll
            for (int j = 0; j < 8; ++j) {
                int k = kb + 8 + j;
                if (k >= nsteps) break;           // uniform across block
                BSTEP(k, qbB[j], q0B[j], qNB[j]);
            }
            // refill B <- k = kb+24 .. kb+31
            if (kb + 24 < nsteps) {
                #pragma unroll
                for (int j = 0; j < 8; ++j) {
                    int tq = imax(il - 1 - (kb + 24 + j), 0);
                    qbB[j] = __ldg(pbase + (long long)tq * C);
                    q0B[j] = __ldg(pl0p  + (long long)tq * C);
                    qNB[j] = __ldg(plNp  + (long long)tq * C);
                }
            }
        }
        #undef BSTEP

        float* gb = g_beta + b * 520;
        gb[2 * tid + 1] = bo;
        gb[2 * tid + 2] = be;
        if (tid == 0) gb[0] = b0;
    }

    // ---- rendezvous: second finisher combines ------------------------------
    __threadfence();
    if (tid == 0) sflag = atomicInc(&g_done[b], 1u);
    __syncthreads();
    if (sflag != 1u) return;

    {
        volatile float* ga = g_alpha + b * 520;
        volatile float* gb = g_beta  + b * 520;
        float v1 = ga[tid]       + gb[tid];
        float v2 = ga[tid + 256] + gb[tid + 256];
        float v3 = (tid == 0) ? (ga[512] + gb[512]) : (NEGV + NEGV);

        float m = fmaxf(v1, fmaxf(v2, v3));
        #pragma unroll
        for (int o = 16; o; o >>= 1)
            m = fmaxf(m, __shfl_xor_sync(0xffffffffu, m, o));
        if (lane == 0) red[w] = m;
        __syncthreads();
        float bm = red[0];
        #pragma unroll
        for (int i = 1; i < 8; ++i) bm = fmaxf(bm, red[i]);

        float s = ex2(v1 - bm) + ex2(v2 - bm) + ex2(v3 - bm);
        #pragma unroll
        for (int o = 16; o; o >>= 1)
            s += __shfl_xor_sync(0xffffffffu, s, o);
        __syncthreads();             // red reuse
        if (lane == 0) red[w] = s;
        __syncthreads();

        if (tid == 0) {
            float ssum = 0.f;
            #pragma unroll
            for (int i = 0; i < 8; ++i) ssum += red[i];
            g_loss[b] = -(bm + lg2(ssum)) * LN2F;
            __threadfence();
            unsigned old = atomicInc(&g_ctr, (unsigned)(B - 1));   // wraps to 0
            if (old == (unsigned)(B - 1)) {
                __threadfence();
                volatile float* gl = g_loss;
                float acc = 0.f;
                for (int i = 0; i < B; ++i) acc += gl[i];
                out[loss_idx] = acc / (float)B;
            }
        }
    }
}

// ---------------------------------------------------------------------------
extern "C" void kernel_launch(void* const* d_in, const int* in_sizes, int n_in,
                              void* d_out, int out_size) {
    const int*   y_true = (const int*)  d_in[0];  // [B, L]
    const float* y_pred = (const float*)d_in[1];  // [B, T, C]
    const int*   il     = (const int*)  d_in[2];  // [B]
    const int*   ll     = (const int*)  d_in[3];  // [B]

    const int B = in_sizes[2];
    const int L = in_sizes[0] / B;                // 256
    const int C = 128;                            // fixed for this problem
    const int T = in_sizes[1] / (B * C);
    float* out = (float*)d_out;

    const int transBlocks = 1344;                 // fill remaining SMs

    ctc_fused_kernel<<<2 * B + transBlocks, L>>>(
        y_pred, y_true, il, ll, out, T, B, C, L,
        (long long)out_size - 1);
}

// round 17
// speedup vs baseline: 1.0920x; 1.0920x over previous
#include <cuda_runtime.h>
#include <math.h>

#define NEGV (-1e30f)
#define LN2F 0.6931471805599453f
#define DPRE 8

// scratch (no cudaMalloc allowed)
__device__ float g_alpha[64 * 520];
__device__ float g_beta[64 * 520];
__device__ float g_loss[4096];
__device__ unsigned g_done[4096];   // 2 incs per b per launch, wraps 0->1->0
__device__ unsigned g_ctr;          // B incs per launch, wraps to 0

__device__ __forceinline__ float ex2(float x) {
    float r; asm("ex2.approx.f32 %0, %1;" : "=f"(r) : "f"(x)); return r;
}
__device__ __forceinline__ float lg2(float x) {
    float r; asm("lg2.approx.f32 %0, %1;" : "=f"(r) : "f"(x)); return r;
}
// CTC half-block barrier (warps 0-7 only; transpose warps never touch it)
#define BAR1() asm volatile("bar.sync 1, 256;" ::: "memory")

// grid-stride log+transpose slice over float4 elements
__device__ __forceinline__ void transpose_slice(
    const float* __restrict__ p, float* __restrict__ out,
    int T, int B, int C, int vt, int vtot) {
    const int c4w = C >> 2;
    const int total4 = T * B * c4w;
    const float4* __restrict__ p4 = (const float4*)p;
    float4* __restrict__ o4 = (float4*)out;
    #pragma unroll 4
    for (int v = vt; v < total4; v += vtot) {
        int c4 = v % c4w;
        int rr = v / c4w;                 // rr = t*B + b
        int b = rr % B;
        int t = rr / B;
        float4 x = p4[((long long)b * T + t) * c4w + c4];
        float4 y;
        y.x = __logf(x.x); y.y = __logf(x.y);
        y.z = __logf(x.z); y.w = __logf(x.w);
        o4[v] = y;
    }
}

// ---------------------------------------------------------------------------
// Fused kernel, grid = 2B + 20 = 148 blocks x 512 threads (1 block / SM):
//   blocks [0, B)    : warps 0-7 CTC forward half,  warps 8-15 transpose slice
//   blocks [B, 2B)   : warps 0-7 CTC backward half, warps 8-15 transpose slice
//   blocks [2B, 148) : all 16 warps transpose
// CTC halves use named barrier 1 (256 threads); transpose warps run free.
// Second finisher of each (fwd, bwd) pair combines: loss = -lse_s(alpha+beta).
// ---------------------------------------------------------------------------
__global__ void __launch_bounds__(512)
ctc_fused_kernel(const float* __restrict__ p,      // [B,T,C]
                 const int* __restrict__ labels,   // [B,L]
                 const int* __restrict__ in_len,   // [B]
                 const int* __restrict__ lab_len,  // [B]
                 float* __restrict__ out,          // [T,B,C] (+ loss at end)
                 int T, int B, int C, int L,
                 long long loss_idx) {
    const int bx  = blockIdx.x;
    const int tid = threadIdx.x;
    const int vtot = 2 * B * 256 + ((int)gridDim.x - 2 * B) * 512;

    if (bx >= 2 * B) {                    // full-block transpose
        int vt = 2 * B * 256 + (bx - 2 * B) * 512 + tid;
        transpose_slice(p, out, T, B, C, vt, vtot);
        return;
    }
    if (tid >= 256) {                     // half-block transpose
        int vt = bx * 256 + (tid - 256);
        transpose_slice(p, out, T, B, C, vt, vtot);
        return;
    }

    // ======================= CTC half (threads 0-255) =======================
    __shared__ float bnd[2][8];
    __shared__ float red[8];
    __shared__ unsigned sflag;

    const bool isFwd = (bx < B);
    const int b    = isFwd ? bx : bx - B;
    const int w    = tid >> 5;
    const int lane = tid & 31;
    const int last = 255;

    int il = in_len[b];  il = il < 1 ? 1 : (il > T ? T : il);
    int ll = lab_len[b]; ll = ll < 1 ? 1 : (ll > L ? L : ll);
    const int tm = (il - 1) >> 1;            // meeting time

    const float* __restrict__ pbase = p + (long long)b * T * C;   // blank col 0

    if (isFwd) {
        // ===== forward: thread owns alpha(2tid)=ae, alpha(2tid+1)=ao ========
        const int   lab = labels[b * L + tid];
        const float ks  = ((tid > 0) && (lab != labels[b * L + tid - 1])) ? 1.0f : 0.0f;
        const float* __restrict__ plabp = pbase + lab;

        float ae, ao, a5 = NEGV;
        {
            float pb0 = __ldg(pbase);
            float pl0 = __ldg(plabp);
            ae = (tid == 0) ? lg2(pb0) : NEGV;
            ao = (tid == 0) ? lg2(pl0) : NEGV;
            if (lane == 31) bnd[1][w] = ao;     // parity for t=1
        }
        float rpb[DPRE], rpl[DPRE];
        #pragma unroll
        for (int j = 0; j < DPRE; ++j) {
            int tt = 1 + j; if (tt > il - 1) tt = il - 1;
            rpb[j] = __ldg(pbase + (long long)tt * C);
            rpl[j] = __ldg(plabp + (long long)tt * C);
        }
        BAR1();

        const int tend = tm + 1;                  // loop t = 1 .. tm
        for (int tb = 1; tb < tend; tb += DPRE) {
            #pragma unroll
            for (int j = 0; j < DPRE; ++j) {
                int t = tb + j;
                if (t >= tend) break;             // uniform across half

                float pb = rpb[j], pl = rpl[j];
                float a_ol = __shfl_up_sync(0xffffffffu, ao, 1);
                if (lane == 0) a_ol = (w > 0) ? bnd[t & 1][w - 1] : NEGV;

                float m  = fmaxf(fmaxf(ae, ao), a_ol);
                float xe = ex2(ae - m);
                float xo = ex2(ao - m);
                float xL = ex2(a_ol - m);
                float ve = m + lg2((xe + xL) * pb);
                float vo = m + lg2((xo + xe + ks * xL) * pl);
                if (tid == last) {                 // state 512, uses OLD ao
                    float m5 = fmaxf(a5, ao);
                    a5 = fmaxf(m5 + lg2((ex2(a5 - m5) + ex2(ao - m5)) * pb), NEGV);
                }
                ae = fmaxf(ve, NEGV);
                ao = fmaxf(vo, NEGV);
                if (lane == 31) bnd[(t + 1) & 1][w] = ao;

                int tp = t + DPRE; if (tp > il - 1) tp = il - 1;
                rpb[j] = __ldg(pbase + (long long)tp * C);
                rpl[j] = __ldg(plabp + (long long)tp * C);
                BAR1();
            }
        }
        float* ga = g_alpha + b * 520;
        ga[2 * tid]     = ae;
        ga[2 * tid + 1] = ao;
        if (tid == last) ga[512] = a5;
    } else {
        // ===== backward: thread owns beta(2tid+1)=bo, beta(2tid+2)=be =======
        const int   lab0 = labels[b * L + tid];
        const int   labN = (tid < last) ? labels[b * L + tid + 1] : lab0;
        const float ksN  = ((tid < last) && (labN != lab0)) ? 1.0f : 0.0f;
        const float* __restrict__ pl0p = pbase + lab0;
        const float* __restrict__ plNp = pbase + labN;

        float bo = (tid == ll - 1) ? 0.0f : NEGV;   // state 2tid+1
        float be = (tid == ll - 1) ? 0.0f : NEGV;   // state 2tid+2
        float b0 = NEGV;                             // state 0 (thread 0)
        if (lane == 0 && w > 0) bnd[0][w] = bo;      // consumed at k=0 by w-1

        const int nsteps = il - 1 - tm;           // k = 0 .. nsteps-1
        float rqb[DPRE], rq0[DPRE], rqN[DPRE];
        #pragma unroll
        for (int j = 0; j < DPRE; ++j) {
            int tt = il - 1 - j; if (tt < 0) tt = 0;
            rqb[j] = __ldg(pbase + (long long)tt * C);
            rq0[j] = __ldg(pl0p  + (long long)tt * C);
            rqN[j] = __ldg(plNp  + (long long)tt * C);
        }
        BAR1();

        for (int kb = 0; kb < nsteps; kb += DPRE) {
            #pragma unroll
            for (int j = 0; j < DPRE; ++j) {
                int k = kb + j;
                if (k >= nsteps) break;           // uniform across half

                float qb = rqb[j], q0 = rq0[j], qN = rqN[j];
                float boN = __shfl_down_sync(0xffffffffu, bo, 1);
                if (lane == 31) boN = (w < 7) ? bnd[k & 1][w + 1] : NEGV;

                float m  = fmaxf(fmaxf(bo, be), boN);
                float xo = ex2(bo - m);
                float xe = ex2(be - m);
                float xN = ex2(boN - m);
                float t1 = xe * qb;
                float t2 = xN * qN;
                float nbo = m + lg2(xo * q0 + t1 + ksN * t2);
                float nbe = m + lg2(t1 + t2);
                if (tid == 0) {                    // state 0, uses OLD bo
                    float mb = fmaxf(b0, bo);
                    b0 = fmaxf(mb + lg2(ex2(b0 - mb) * qb + ex2(bo - mb) * q0), NEGV);
                }
                bo = fmaxf(nbo, NEGV);
                be = fmaxf(nbe, NEGV);
                if (lane == 0 && w > 0) bnd[(k + 1) & 1][w] = bo;

                int tq = il - 1 - (k + DPRE); if (tq < 0) tq = 0;
                rqb[j] = __ldg(pbase + (long long)tq * C);
                rq0[j] = __ldg(pl0p  + (long long)tq * C);
                rqN[j] = __ldg(plNp  + (long long)tq * C);
                BAR1();
            }
        }
        float* gb = g_beta + b * 520;
        gb[2 * tid + 1] = bo;
        gb[2 * tid + 2] = be;
        if (tid == 0) gb[0] = b0;
    }

    // ---- rendezvous: second finisher combines ------------------------------
    __threadfence();
    if (tid == 0) sflag = atomicInc(&g_done[b], 1u);
    BAR1();
    if (sflag != 1u) return;

    {
        volatile float* ga = g_alpha + b * 520;
        volatile float* gb = g_beta  + b * 520;
        float v1 = ga[tid]       + gb[tid];
        float v2 = ga[tid + 256] + gb[tid + 256];
        float v3 = (tid == 0) ? (ga[512] + gb[512]) : (NEGV + NEGV);

        float m = fmaxf(v1, fmaxf(v2, v3));
        #pragma unroll
        for (int o = 16; o; o >>= 1)
            m = fmaxf(m, __shfl_xor_sync(0xffffffffu, m, o));
        if (lane == 0) red[w] = m;
        BAR1();
        float bm = red[0];
        #pragma unroll
        for (int i = 1; i < 8; ++i) bm = fmaxf(bm, red[i]);

        float s = ex2(v1 - bm) + ex2(v2 - bm) + ex2(v3 - bm);
        #pragma unroll
        for (int o = 16; o; o >>= 1)
            s += __shfl_xor_sync(0xffffffffu, s, o);
        BAR1();                      // red reuse
        if (lane == 0) red[w] = s;
        BAR1();

        if (tid == 0) {
            float ssum = 0.f;
            #pragma unroll
            for (int i = 0; i < 8; ++i) ssum += red[i];
            g_loss[b] = -(bm + lg2(ssum)) * LN2F;
            __threadfence();
            unsigned old = atomicInc(&g_ctr, (unsigned)(B - 1));   // wraps to 0
            if (old == (unsigned)(B - 1)) {
                __threadfence();
                volatile float* gl = g_loss;
                float acc = 0.f;
                for (int i = 0; i < B; ++i) acc += gl[i];
                out[loss_idx] = acc / (float)B;
            }
        }
    }
}

// ---------------------------------------------------------------------------
extern "C" void kernel_launch(void* const* d_in, const int* in_sizes, int n_in,
                              void* d_out, int out_size) {
    const int*   y_true = (const int*)  d_in[0];  // [B, L]
    const float* y_pred = (const float*)d_in[1];  // [B, T, C]
    const int*   il     = (const int*)  d_in[2];  // [B]
    const int*   ll     = (const int*)  d_in[3];  // [B]

    const int B = in_sizes[2];
    const int L = in_sizes[0] / B;                // 256
    const int C = 128;                            // fixed for this problem
    const int T = in_sizes[1] / (B * C);
    float* out = (float*)d_out;

    // grid = 2B + 20 = 148 blocks -> exactly one block per SM in wave 1
    const int transBlocks = 20;

    ctc_fused_kernel<<<2 * B + transBlocks, 512>>>(
        y_pred, y_true, il, ll, out, T, B, C, L,
        (long long)out_size - 1);
}